// round 1
// baseline (speedup 1.0000x reference)
#include <cuda_runtime.h>
#include <cuda_bf16.h>
#include <cstdint>

// Problem constants (fixed by setup_inputs)
#define NMAX   131072      // B*INPUT_LEN
#define EMAX   4194304
#define ILEN   4096        // input_len (power of 2)
#define PLEN   1024        // pred_len  (power of 2)

// Scratch: __device__ globals (no allocation allowed)
__device__ float  g_deg [NMAX];
__device__ float  g_dinv[NMAX];
__device__ float4 g_hs  [NMAX];   // (x@W1) * dinv[src], padded, w=0
__device__ float4 g_agg1[NMAX];   // layer1 aggregator (init with self-loop term)
__device__ float  g_t   [NMAX];   // layer2 pre-scaled messages

// ---------------------------------------------------------------------------
// K1: deg = 1 (self loop)
__global__ void k_init_deg(int N) {
    int i = blockIdx.x * blockDim.x + threadIdx.x;
    if (i < N) g_deg[i] = 1.0f;
}

// K2: deg[dst] += 1 per edge (vectorized int4 over dst row)
__global__ void k_deg(const int* __restrict__ dst, int E) {
    int stride = gridDim.x * blockDim.x;
    int i = blockIdx.x * blockDim.x + threadIdx.x;
    int E4 = E >> 2;
    const int4* dst4 = (const int4*)dst;
    for (int e = i; e < E4; e += stride) {
        int4 d = dst4[e];
        atomicAdd(&g_deg[d.x], 1.0f);
        atomicAdd(&g_deg[d.y], 1.0f);
        atomicAdd(&g_deg[d.z], 1.0f);
        atomicAdd(&g_deg[d.w], 1.0f);
    }
    // tail (E not multiple of 4)
    for (int e = (E4 << 2) + i; e < E; e += stride)
        atomicAdd(&g_deg[dst[e]], 1.0f);
}

// K3: dinv = rsqrt(deg)  (deg >= 1 always due to self loop)
__global__ void k_dinv(int N) {
    int i = blockIdx.x * blockDim.x + threadIdx.x;
    if (i < N) g_dinv[i] = rsqrtf(g_deg[i]);
}

// K4: one warp per node: h = x@W1 (256->3); store hs = h*dinv, agg1 = h*dinv^2
__global__ void k_linear1(const float4* __restrict__ X4,
                          const float* __restrict__ W1, int N) {
    int lane   = threadIdx.x & 31;
    int warp   = (blockIdx.x * blockDim.x + threadIdx.x) >> 5;
    int nwarps = (gridDim.x * blockDim.x) >> 5;

    // Each lane owns float4 chunks c0=lane, c1=lane+32 (features 4c..4c+3).
    // Preload the 24 needed weights into registers, reused across all nodes.
    float wa[4][3], wb[4][3];
#pragma unroll
    for (int j = 0; j < 4; j++)
#pragma unroll
        for (int k = 0; k < 3; k++) {
            wa[j][k] = W1[(4 * lane        + j) * 3 + k];
            wb[j][k] = W1[(4 * (lane + 32) + j) * 3 + k];
        }

    for (int n = warp; n < N; n += nwarps) {
        float4 xa = X4[(size_t)n * 64 + lane];
        float4 xb = X4[(size_t)n * 64 + lane + 32];
        float a0, a1, a2;
        a0 = xa.x*wa[0][0] + xa.y*wa[1][0] + xa.z*wa[2][0] + xa.w*wa[3][0]
           + xb.x*wb[0][0] + xb.y*wb[1][0] + xb.z*wb[2][0] + xb.w*wb[3][0];
        a1 = xa.x*wa[0][1] + xa.y*wa[1][1] + xa.z*wa[2][1] + xa.w*wa[3][1]
           + xb.x*wb[0][1] + xb.y*wb[1][1] + xb.z*wb[2][1] + xb.w*wb[3][1];
        a2 = xa.x*wa[0][2] + xa.y*wa[1][2] + xa.z*wa[2][2] + xa.w*wa[3][2]
           + xb.x*wb[0][2] + xb.y*wb[1][2] + xb.z*wb[2][2] + xb.w*wb[3][2];
#pragma unroll
        for (int off = 16; off; off >>= 1) {
            a0 += __shfl_xor_sync(0xffffffffu, a0, off);
            a1 += __shfl_xor_sync(0xffffffffu, a1, off);
            a2 += __shfl_xor_sync(0xffffffffu, a2, off);
        }
        if (lane == 0) {
            float dv = g_dinv[n];
            float4 hs = make_float4(a0 * dv, a1 * dv, a2 * dv, 0.0f);
            g_hs[n] = hs;
            g_agg1[n] = make_float4(hs.x * dv, hs.y * dv, hs.z * dv, 0.0f);
        }
    }
}

// K5: layer-1 scatter: agg1[dst] += hs[src] * dinv[dst]   (vector red, 1/edge)
__global__ void k_edge1(const int* __restrict__ ei, int E) {
    int stride = gridDim.x * blockDim.x;
    for (int e = blockIdx.x * blockDim.x + threadIdx.x; e < E; e += stride) {
        int s = ei[e];
        int d = ei[E + e];
        float4 h = g_hs[s];
        float nd = g_dinv[d];
        size_t p = __cvta_generic_to_global(&g_agg1[d]);
        asm volatile("red.global.add.v4.f32 [%0], {%1, %2, %3, %4};"
                     :: "l"(p), "f"(h.x * nd), "f"(h.y * nd), "f"(h.z * nd),
                        "f"(0.0f)
                     : "memory");
    }
}

// K6: finalize layer1 (relu(+b1)), apply W2, pre-scale t = h2*dinv,
//     and seed d_out with self-loop term + b2 for output-window nodes.
__global__ void k_final1(const float* __restrict__ b1,
                         const float* __restrict__ W2,
                         const float* __restrict__ b2,
                         float* __restrict__ out, int N) {
    int n = blockIdx.x * blockDim.x + threadIdx.x;
    if (n >= N) return;
    float4 a = g_agg1[n];
    float o0 = fmaxf(a.x + b1[0], 0.0f);
    float o1 = fmaxf(a.y + b1[1], 0.0f);
    float o2 = fmaxf(a.z + b1[2], 0.0f);
    float h2 = o0 * W2[0] + o1 * W2[1] + o2 * W2[2];
    float dv = g_dinv[n];
    g_t[n] = h2 * dv;
    int r = n & (ILEN - 1);
    if (r < PLEN)
        out[(n >> 12) * PLEN + r] = h2 * dv * dv + b2[0];
}

// K7: layer-2 scatter, filtered to output-window destinations, into d_out.
__global__ void k_edge2(const int* __restrict__ ei, float* __restrict__ out,
                        int E) {
    int stride = gridDim.x * blockDim.x;
    for (int e = blockIdx.x * blockDim.x + threadIdx.x; e < E; e += stride) {
        int d = ei[E + e];
        int r = d & (ILEN - 1);
        if (r < PLEN) {
            int s = ei[e];
            float v = g_t[s] * g_dinv[d];
            atomicAdd(&out[(d >> 12) * PLEN + r], v);
        }
    }
}

// ---------------------------------------------------------------------------
extern "C" void kernel_launch(void* const* d_in, const int* in_sizes, int n_in,
                              void* d_out, int out_size) {
    const float* X   = (const float*)d_in[0];   // [N,256]
    const float* W1  = (const float*)d_in[1];   // [256,3]
    const float* b1  = (const float*)d_in[2];   // [3]
    const float* W2  = (const float*)d_in[3];   // [3,1]
    const float* b2  = (const float*)d_in[4];   // [1]
    const int*   ei  = (const int*)d_in[5];     // [2,E]
    float*       out = (float*)d_out;

    int N = in_sizes[0] / 256;
    int E = in_sizes[5] / 2;

    const int T = 256;
    int nb_node = (N + T - 1) / T;

    k_init_deg<<<nb_node, T>>>(N);
    k_deg<<<2048, T>>>(ei + E, E);
    k_dinv<<<nb_node, T>>>(N);
    k_linear1<<<1024, T>>>((const float4*)X, W1, N);
    k_edge1<<<8192, T>>>(ei, E);
    k_final1<<<nb_node, T>>>(b1, W2, b2, out, N);
    k_edge2<<<8192, T>>>(ei, out, E);
}